// round 10
// baseline (speedup 1.0000x reference)
#include <cuda_runtime.h>
#include <cstdint>

// QLoRA rank-2 fused kernel (int32-widened quant weights):
//   h[r]   = a_scale[r] * sum_d x[row,d] * a_q[r,d]
//   out[d] = 0.5 * b_scale[d] * (h0 * b_q[d,0] + h1 * b_q[d,1])
//
// The harness widens int8 inputs to int32 buffers (its dtype set is
// {float32, int32, bfloat16}), so a_q / b_q are read as const int*.
//
// Each CTA (256 threads) processes R_PER_CTA=8 rows. Weights are
// dequantized into REGISTERS once per CTA (a: 32 floats, b*bscale: 32
// floats per thread) and reused across the 8 rows, cutting L2 weight
// traffic 8x so the kernel stays DRAM-bound:
//   x read once (256 MB) + out written once (256 MB) ~= 73 us floor.

#define INNER_D   4096
#define NTHREADS  256
#define R_PER_CTA 8

__global__ __launch_bounds__(NTHREADS)
void qlora_fused_kernel(const float* __restrict__ x,
                        const int*   __restrict__ aq,      // [2, 4096] int32
                        const float* __restrict__ ascale,  // [2]
                        const int*   __restrict__ bq,      // [4096, 2] int32
                        const float* __restrict__ bscale,  // [4096]
                        float* __restrict__ out,
                        int nrows) {
    const int t = threadIdx.x;

    // ---- Preload & dequantize weights into registers (once per CTA) ----
    // Each thread owns 16 d-slots: d = t*4 + i*1024 + j, i in 0..3, j in 0..3.
    float  a0v[16], a1v[16];   // a_q rows 0/1 as float
    float2 bwv[16];            // (b_scale[d]*b_q[d,0], b_scale[d]*b_q[d,1])
    #pragma unroll
    for (int i = 0; i < 4; i++) {
        const int d = t * 4 + i * (NTHREADS * 4);
        const int4 aa0 = *reinterpret_cast<const int4*>(aq + d);
        const int4 aa1 = *reinterpret_cast<const int4*>(aq + INNER_D + d);
        const int4 b01 = *reinterpret_cast<const int4*>(bq + 2 * d);      // (d,r0)(d,r1)(d+1,r0)(d+1,r1)
        const int4 b23 = *reinterpret_cast<const int4*>(bq + 2 * d + 4);
        const float4 bs = *reinterpret_cast<const float4*>(bscale + d);
        a0v[i*4+0] = (float)aa0.x;  a0v[i*4+1] = (float)aa0.y;
        a0v[i*4+2] = (float)aa0.z;  a0v[i*4+3] = (float)aa0.w;
        a1v[i*4+0] = (float)aa1.x;  a1v[i*4+1] = (float)aa1.y;
        a1v[i*4+2] = (float)aa1.z;  a1v[i*4+3] = (float)aa1.w;
        bwv[i*4+0] = make_float2(bs.x * (float)b01.x, bs.x * (float)b01.y);
        bwv[i*4+1] = make_float2(bs.y * (float)b01.z, bs.y * (float)b01.w);
        bwv[i*4+2] = make_float2(bs.z * (float)b23.x, bs.z * (float)b23.y);
        bwv[i*4+3] = make_float2(bs.w * (float)b23.z, bs.w * (float)b23.w);
    }
    // fold a_scale and lora_alpha/rank = 0.5 (broadcast load, L2-resident)
    const float as0 = ascale[0] * 0.5f;
    const float as1 = ascale[1] * 0.5f;

    __shared__ float sh0[NTHREADS / 32];
    __shared__ float sh1[NTHREADS / 32];
    __shared__ float hsh[2];
    const int wid = t >> 5, lid = t & 31;

    const int row0 = blockIdx.x * R_PER_CTA;

    for (int r = 0; r < R_PER_CTA; r++) {
        const int row = row0 + r;
        if (row >= nrows) break;
        const float* xr = x + (size_t)row * INNER_D;

        // ---- Phase 1: rank-2 dot products over the row ----
        float4 xv[4];
        #pragma unroll
        for (int i = 0; i < 4; i++)
            xv[i] = *reinterpret_cast<const float4*>(xr + t * 4 + i * (NTHREADS * 4));

        float s0 = 0.f, s1 = 0.f;
        #pragma unroll
        for (int i = 0; i < 4; i++) {
            s0 = fmaf(xv[i].x, a0v[i*4+0], s0);
            s0 = fmaf(xv[i].y, a0v[i*4+1], s0);
            s0 = fmaf(xv[i].z, a0v[i*4+2], s0);
            s0 = fmaf(xv[i].w, a0v[i*4+3], s0);
            s1 = fmaf(xv[i].x, a1v[i*4+0], s1);
            s1 = fmaf(xv[i].y, a1v[i*4+1], s1);
            s1 = fmaf(xv[i].z, a1v[i*4+2], s1);
            s1 = fmaf(xv[i].w, a1v[i*4+3], s1);
        }

        // ---- Block reduce (warp shuffle + smem) ----
        #pragma unroll
        for (int o = 16; o > 0; o >>= 1) {
            s0 += __shfl_xor_sync(0xffffffffu, s0, o);
            s1 += __shfl_xor_sync(0xffffffffu, s1, o);
        }
        if (lid == 0) { sh0[wid] = s0; sh1[wid] = s1; }
        __syncthreads();
        if (t == 0) {
            float h0 = 0.f, h1 = 0.f;
            #pragma unroll
            for (int w = 0; w < NTHREADS / 32; w++) { h0 += sh0[w]; h1 += sh1[w]; }
            hsh[0] = h0 * as0;
            hsh[1] = h1 * as1;
        }
        __syncthreads();
        const float h0 = hsh[0];
        const float h1 = hsh[1];
        __syncthreads();   // protect sh/hsh reuse next iteration

        // ---- Phase 2: rank-2 expansion (weights already in registers) ----
        float* outr = out + (size_t)row * INNER_D;
        #pragma unroll
        for (int i = 0; i < 4; i++) {
            float4 o;
            o.x = fmaf(h0, bwv[i*4+0].x, h1 * bwv[i*4+0].y);
            o.y = fmaf(h0, bwv[i*4+1].x, h1 * bwv[i*4+1].y);
            o.z = fmaf(h0, bwv[i*4+2].x, h1 * bwv[i*4+2].y);
            o.w = fmaf(h0, bwv[i*4+3].x, h1 * bwv[i*4+3].y);
            *reinterpret_cast<float4*>(outr + t * 4 + i * (NTHREADS * 4)) = o;
        }
    }
}

extern "C" void kernel_launch(void* const* d_in, const int* in_sizes, int n_in,
                              void* d_out, int out_size) {
    // Bind inputs by element count (robust to metadata ordering):
    //   67108864 -> x_in, 2 -> a_scale, 4096 -> b_scale,
    //   8192 (x2) -> a_q (first), b_q (second)  [a_q precedes b_q in both
    //   dict order and alphabetical order].
    const float* x      = nullptr;
    const int*   aq     = nullptr;
    const float* ascale = nullptr;
    const int*   bq     = nullptr;
    const float* bscale = nullptr;

    for (int i = 0; i < n_in; i++) {
        const int sz = in_sizes[i];
        if (sz == 2) {
            ascale = (const float*)d_in[i];
        } else if (sz == 4096) {
            bscale = (const float*)d_in[i];
        } else if (sz == 8192) {
            if (aq == nullptr) aq = (const int*)d_in[i];
            else               bq = (const int*)d_in[i];
        } else {
            x = (const float*)d_in[i];
        }
    }

    float* out = (float*)d_out;
    const int nrows = out_size / INNER_D;            // 16384
    const int grid  = (nrows + R_PER_CTA - 1) / R_PER_CTA;  // 2048
    qlora_fused_kernel<<<grid, NTHREADS>>>(x, aq, ascale, bq, bscale, out, nrows);
}